// round 14
// baseline (speedup 1.0000x reference)
#include <cuda_runtime.h>
#include <cuda_bf16.h>
#include <cuda_fp16.h>
#include <math.h>
#include <stdint.h>

// Dims fixed by dataset: B=2,V=8,T=512,D=1024,H=4096 -> M=8192 rows.
#define M_TOK 8192
#define DIM   1024
#define HID   4096

// ---------------- scratch (device globals) --------------------------------------
__device__ float    g_z [(size_t)M_TOK * DIM];   // z fp32 (for residual)
__device__ uint16_t g_xh[(size_t)M_TOK * DIM];   // fp16 hi of x
__device__ uint16_t g_xl[(size_t)M_TOK * DIM];   // fp16 lo of x
__device__ uint16_t g_zh[(size_t)M_TOK * DIM];   // bf16(z) for GEMM1
__device__ uint16_t g_hh[(size_t)M_TOK * HID];   // bf16(h) for GEMM2
__device__ uint16_t g_tf [(size_t)DIM * DIM];    // fp16(theta^T) [N=D,K=D]
__device__ uint16_t g_w1h[(size_t)HID * DIM];    // bf16(W1^T) [H,D]
__device__ uint16_t g_w2h[(size_t)DIM * HID];    // bf16(W2^T) [D,H]

// ---------------- helpers -------------------------------------------------------
__device__ __forceinline__ uint32_t smem_u32(const void* p) {
    uint32_t a;
    asm("{ .reg .u64 t; cvta.to.shared.u64 t, %1; cvt.u32.u64 %0, t; }" : "=r"(a) : "l"(p));
    return a;
}

__device__ __forceinline__ float gelu_exact(float v) {
    return 0.5f * v * (1.0f + erff(v * 0.70710678118654752f));
}

__device__ __forceinline__ uint16_t to_bf(float v) {
    __nv_bfloat16 b = __float2bfloat16_rn(v);
    return *reinterpret_cast<uint16_t*>(&b);
}

__device__ __forceinline__ uint16_t to_h16(float v) {
    __half h = __float2half_rn(v);
    return *reinterpret_cast<uint16_t*>(&h);
}

__device__ __forceinline__ void split_h16(float v, uint16_t& h, uint16_t& l) {
    __half hh = __float2half_rn(v);
    float fh = __half2float(hh);
    __half hl = __float2half_rn(v - fh);
    h = *reinterpret_cast<uint16_t*>(&hh);
    l = *reinterpret_cast<uint16_t*>(&hl);
}

__device__ __forceinline__ void ldsm4(uint32_t (&r)[4], uint32_t addr) {
    asm volatile("ldmatrix.sync.aligned.m8n8.x4.shared.b16 {%0,%1,%2,%3}, [%4];"
        : "=r"(r[0]), "=r"(r[1]), "=r"(r[2]), "=r"(r[3]) : "r"(addr));
}

__device__ __forceinline__ void mma_bf16(float (&c)[4], const uint32_t (&a)[4],
                                         uint32_t b0, uint32_t b1) {
    asm volatile(
        "mma.sync.aligned.m16n8k16.row.col.f32.bf16.bf16.f32 "
        "{%0,%1,%2,%3}, {%4,%5,%6,%7}, {%8,%9}, {%0,%1,%2,%3};"
        : "+f"(c[0]), "+f"(c[1]), "+f"(c[2]), "+f"(c[3])
        : "r"(a[0]), "r"(a[1]), "r"(a[2]), "r"(a[3]), "r"(b0), "r"(b1));
}

__device__ __forceinline__ void mma_f16(float (&c)[4], const uint32_t (&a)[4],
                                        uint32_t b0, uint32_t b1) {
    asm volatile(
        "mma.sync.aligned.m16n8k16.row.col.f32.f16.f16.f32 "
        "{%0,%1,%2,%3}, {%4,%5,%6,%7}, {%8,%9}, {%0,%1,%2,%3};"
        : "+f"(c[0]), "+f"(c[1]), "+f"(c[2]), "+f"(c[3])
        : "r"(a[0]), "r"(a[1]), "r"(a[2]), "r"(a[3]), "r"(b0), "r"(b1));
}

#define CP16(dst, src) \
    asm volatile("cp.async.cg.shared.global [%0], [%1], 16;" :: "r"(dst), "l"(src))
#define CP_COMMIT() asm volatile("cp.async.commit_group;")
#define CP_WAIT2()  asm volatile("cp.async.wait_group 2;")

// ---------------- pre-pass kernels (3 launches) ---------------------------------
__global__ __launch_bounds__(256) void convert_split_f16_kernel(
    const float* __restrict__ in, uint16_t* __restrict__ hi, uint16_t* __restrict__ lo)
{
    size_t i = ((size_t)blockIdx.x * 256 + threadIdx.x) * 4;
    float4 v = *reinterpret_cast<const float4*>(in + i);
    ushort4 h, l;
    split_h16(v.x, h.x, l.x);
    split_h16(v.y, h.y, l.y);
    split_h16(v.z, h.z, l.z);
    split_h16(v.w, h.w, l.w);
    *reinterpret_cast<ushort4*>(hi + i) = h;
    *reinterpret_cast<ushort4*>(lo + i) = l;
}

__global__ __launch_bounds__(256) void transpose_f16_kernel(
    const float* __restrict__ W, uint16_t* __restrict__ oh, int K, int N)
{
    __shared__ float tile[32][33];
    const int tx = threadIdx.x, ty = threadIdx.y;
    const int n0 = blockIdx.x * 32, k0 = blockIdx.y * 32;
#pragma unroll
    for (int i = 0; i < 4; i++)
        tile[ty + i * 8][tx] = W[(size_t)(k0 + ty + i * 8) * N + (n0 + tx)];
    __syncthreads();
#pragma unroll
    for (int i = 0; i < 4; i++) {
        float v = tile[tx][ty + i * 8];
        oh[(size_t)(n0 + ty + i * 8) * K + (k0 + tx)] = to_h16(v);
    }
}

__global__ __launch_bounds__(256) void transpose_bf_dual_kernel(
    const float* __restrict__ W1, uint16_t* __restrict__ o1, int K1, int N1,
    const float* __restrict__ W2, uint16_t* __restrict__ o2, int K2, int N2)
{
    const float* W = (blockIdx.z == 0) ? W1 : W2;
    uint16_t*   o  = (blockIdx.z == 0) ? o1 : o2;
    const int K    = (blockIdx.z == 0) ? K1 : K2;
    const int N    = (blockIdx.z == 0) ? N1 : N2;
    const int nx = N / 32;
    const int b  = blockIdx.x;
    const int bxx = b % nx, byy = b / nx;

    __shared__ float tile[32][33];
    const int tx = threadIdx.x, ty = threadIdx.y;
    const int n0 = bxx * 32, k0 = byy * 32;
#pragma unroll
    for (int i = 0; i < 4; i++)
        tile[ty + i * 8][tx] = W[(size_t)(k0 + ty + i * 8) * N + (n0 + tx)];
    __syncthreads();
#pragma unroll
    for (int i = 0; i < 4; i++) {
        float v = tile[tx][ty + i * 8];
        o[(size_t)(n0 + ty + i * 8) * K + (k0 + tx)] = to_bf(v);
    }
}

// ---------------- unified big-tile GEMM -----------------------------------------
// C[M,N] = A @ B^T; A [M,K], B [N,K], 16-bit K-major inputs.
// CTA tile 128m x 256n, BK=32, 8 warps, warp tile 64x64 (grid 2m x 4n).
// 3-stage cp.async pipeline. Rows 64B, 16B chunk c stored at c ^ ((row>>1)&3).
// TERMS=2 (fp16 split x, fp16 theta): z = Ahi@B + Alo@B.
//   Stage 32KB: Ahi[0,8K) Alo[8K,16K) B[16K,32K)
// TERMS=1 (bf16): Stage 24KB: A[0,8K) B[8K,24K)
// OP 0: write fp32 + bf16        (z)
// OP 1: +bias, exact GELU, bf16  (h)
// OP 2: +bias, fp32              (y -> d_out)
template <int OP, int TERMS>
__global__ __launch_bounds__(256, 1) void gemm_big(
    const uint16_t* __restrict__ Ah, const uint16_t* __restrict__ Al,
    const uint16_t* __restrict__ B,
    const float* __restrict__ bias,
    float* __restrict__ outF, uint16_t* __restrict__ outH,
    int K, int N)
{
    constexpr uint32_t STG  = (TERMS == 2) ? 32768u : 24576u;
    constexpr uint32_t BOFF = (TERMS == 2) ? 16384u : 8192u;

    extern __shared__ __align__(1024) char smem[];
    const uint32_t sb = smem_u32(smem);
    const int tid = threadIdx.x;
    const int wid = tid >> 5, lane = tid & 31;
    const int bx = blockIdx.x, by = blockIdx.y;
    const int NKC = K >> 5;

    const uint16_t* A0h = Ah + (size_t)(by * 128) * K;
    const uint16_t* A0l = (TERMS == 2) ? (Al + (size_t)(by * 128) * K) : nullptr;
    const uint16_t* B0  = B + (size_t)(bx * 256) * K;

    const int srow0 = tid >> 2, sc = tid & 3;          // srow0: 0..63
    auto swz = [&](int r) -> uint32_t {
        return (uint32_t)(r * 64 + ((sc ^ ((r >> 1) & 3)) << 4));
    };
    const uint32_t a_sd0 = swz(srow0), a_sd1 = swz(srow0 + 64);
    const uint32_t b_sd0 = swz(srow0), b_sd1 = swz(srow0 + 64);
    const uint32_t b_sd2 = swz(srow0 + 128), b_sd3 = swz(srow0 + 192);

    auto issue = [&](int s) {
        if (s < NKC) {
            const int kof = s * 32 + sc * 8;
            const uint32_t base = sb + (uint32_t)(s % 3) * STG;
            const size_t oa0 = (size_t)srow0 * K + kof;
            const size_t oa1 = (size_t)(srow0 + 64) * K + kof;
            CP16(base + a_sd0, A0h + oa0);
            CP16(base + a_sd1, A0h + oa1);
            if (TERMS == 2) {
                CP16(base + 8192 + a_sd0, A0l + oa0);
                CP16(base + 8192 + a_sd1, A0l + oa1);
            }
            CP16(base + BOFF + b_sd0, B0 + oa0);
            CP16(base + BOFF + b_sd1, B0 + oa1);
            CP16(base + BOFF + b_sd2, B0 + (size_t)(srow0 + 128) * K + kof);
            CP16(base + BOFF + b_sd3, B0 + (size_t)(srow0 + 192) * K + kof);
        }
        CP_COMMIT();
    };

    issue(0);
    issue(1);
    issue(2);

    const int wm = wid >> 2;          // 0..1 -> m offset wm*64
    const int wn = wid & 3;           // 0..3 -> n offset wn*64
    const int a_r = (lane & 7) + ((lane >> 3) & 1) * 8;
    const int a_c = lane >> 4;
    const int b_r = (lane & 7) + ((lane >> 4) << 3);
    const int b_c = (lane >> 3) & 1;

    float c[4][8][4];
#pragma unroll
    for (int mf = 0; mf < 4; mf++)
#pragma unroll
        for (int nf = 0; nf < 8; nf++)
#pragma unroll
            for (int j = 0; j < 4; j++) c[mf][nf][j] = 0.0f;

    for (int kc = 0; kc < NKC; kc++) {
        CP_WAIT2();
        __syncthreads();
        const uint32_t buf = sb + (uint32_t)(kc % 3) * STG;
#pragma unroll
        for (int ks = 0; ks < 2; ks++) {
            uint32_t af[4][4];
#pragma unroll
            for (int mf = 0; mf < 4; mf++) {
                const int r = wm * 64 + mf * 16 + a_r;
                const uint32_t ad = buf + (uint32_t)(r * 64 +
                                   (((2 * ks + a_c) ^ ((r >> 1) & 3)) << 4));
                ldsm4(af[mf], ad);
            }
#pragma unroll
            for (int g = 0; g < 4; g++) {
                const int r = wn * 64 + g * 16 + b_r;
                const uint32_t bd = buf + BOFF + (uint32_t)(r * 64 +
                                   (((2 * ks + b_c) ^ ((r >> 1) & 3)) << 4));
                uint32_t b[4];
                ldsm4(b, bd);
                if (TERMS == 2) {
#pragma unroll
                    for (int mf = 0; mf < 4; mf++) {
                        mma_f16(c[mf][2 * g + 0], af[mf], b[0], b[1]);
                        mma_f16(c[mf][2 * g + 1], af[mf], b[2], b[3]);
                    }
                } else {
#pragma unroll
                    for (int mf = 0; mf < 4; mf++) {
                        mma_bf16(c[mf][2 * g + 0], af[mf], b[0], b[1]);
                        mma_bf16(c[mf][2 * g + 1], af[mf], b[2], b[3]);
                    }
                }
            }
            if (TERMS == 2) {
                uint32_t alf[4][4];
#pragma unroll
                for (int mf = 0; mf < 4; mf++) {
                    const int r = wm * 64 + mf * 16 + a_r;
                    const uint32_t ad = buf + 8192 + (uint32_t)(r * 64 +
                                       (((2 * ks + a_c) ^ ((r >> 1) & 3)) << 4));
                    ldsm4(alf[mf], ad);
                }
#pragma unroll
                for (int g = 0; g < 4; g++) {
                    const int r = wn * 64 + g * 16 + b_r;
                    const uint32_t bd = buf + BOFF + (uint32_t)(r * 64 +
                                       (((2 * ks + b_c) ^ ((r >> 1) & 3)) << 4));
                    uint32_t b[4];
                    ldsm4(b, bd);
#pragma unroll
                    for (int mf = 0; mf < 4; mf++) {
                        mma_f16(c[mf][2 * g + 0], alf[mf], b[0], b[1]);
                        mma_f16(c[mf][2 * g + 1], alf[mf], b[2], b[3]);
                    }
                }
            }
        }
        __syncthreads();
        issue(kc + 3);
    }

    // ---- epilogue: fragments -> GMEM (coalesced 32B sectors per lane-quad) ----
    const int r0 = by * 128 + wm * 64 + (lane >> 2);
    const int c0 = bx * 256 + wn * 64 + (lane & 3) * 2;

#pragma unroll
    for (int mf = 0; mf < 4; mf++) {
#pragma unroll
        for (int nf = 0; nf < 8; nf++) {
            const int col = c0 + nf * 8;
            float bv0 = 0.0f, bv1 = 0.0f;
            if (OP >= 1) { bv0 = bias[col]; bv1 = bias[col + 1]; }
#pragma unroll
            for (int half = 0; half < 2; half++) {
                const int row = r0 + mf * 16 + half * 8;
                float v0 = c[mf][nf][2 * half + 0];
                float v1 = c[mf][nf][2 * half + 1];
                const size_t o = (size_t)row * N + col;
                if (OP == 0) {
                    *reinterpret_cast<float2*>(outF + o) = make_float2(v0, v1);
                    *reinterpret_cast<uint32_t*>(outH + o) =
                        (uint32_t)to_bf(v0) | ((uint32_t)to_bf(v1) << 16);
                } else if (OP == 1) {
                    v0 = gelu_exact(v0 + bv0);
                    v1 = gelu_exact(v1 + bv1);
                    *reinterpret_cast<uint32_t*>(outH + o) =
                        (uint32_t)to_bf(v0) | ((uint32_t)to_bf(v1) << 16);
                } else {
                    *reinterpret_cast<float2*>(outF + o) = make_float2(v0 + bv0, v1 + bv1);
                }
            }
        }
    }
}

// ---------------- LayerNorm + residual -----------------------------------------
__global__ __launch_bounds__(256) void ln_residual_kernel(
    const float* __restrict__ Z,
    const float* __restrict__ gamma, const float* __restrict__ beta,
    const float* __restrict__ alpha, float* __restrict__ out)
{
    const int row = blockIdx.x;
    const int tid = threadIdx.x;
    float4* orow = reinterpret_cast<float4*>(out + (size_t)row * DIM);
    const float4* zrow = reinterpret_cast<const float4*>(Z + (size_t)row * DIM);

    float4 v = orow[tid];

    __shared__ float red1[8];
    __shared__ float red2[8];

    float s = v.x + v.y + v.z + v.w;
#pragma unroll
    for (int o = 16; o > 0; o >>= 1) s += __shfl_xor_sync(0xffffffffu, s, o);
    if ((tid & 31) == 0) red1[tid >> 5] = s;
    __syncthreads();
    float tot = 0.0f;
#pragma unroll
    for (int i = 0; i < 8; i++) tot += red1[i];
    const float mu = tot * (1.0f / (float)DIM);

    const float dx = v.x - mu, dy = v.y - mu, dz = v.z - mu, dw = v.w - mu;
    float ss = dx * dx + dy * dy + dz * dz + dw * dw;
#pragma unroll
    for (int o = 16; o > 0; o >>= 1) ss += __shfl_xor_sync(0xffffffffu, ss, o);
    if ((tid & 31) == 0) red2[tid >> 5] = ss;
    __syncthreads();
    float tot2 = 0.0f;
#pragma unroll
    for (int i = 0; i < 8; i++) tot2 += red2[i];
    const float rstd = rsqrtf(tot2 * (1.0f / (float)DIM) + 1e-5f);

    const float4 g  = reinterpret_cast<const float4*>(gamma)[tid];
    const float4 b  = reinterpret_cast<const float4*>(beta)[tid];
    const float4 al = reinterpret_cast<const float4*>(alpha)[tid];
    const float4 z4 = zrow[tid];

    float4 o4;
    o4.x = z4.x + tanhf(al.x) * (dx * rstd * g.x + b.x);
    o4.y = z4.y + tanhf(al.y) * (dy * rstd * g.y + b.y);
    o4.z = z4.z + tanhf(al.z) * (dz * rstd * g.z + b.z);
    o4.w = z4.w + tanhf(al.w) * (dw * rstd * g.w + b.w);
    orow[tid] = o4;
}

// ---------------- launch --------------------------------------------------------
extern "C" void kernel_launch(void* const* d_in, const int* in_sizes, int n_in,
                              void* d_out, int out_size)
{
    const float* x       = (const float*)d_in[0];
    const float* theta_Q = (const float*)d_in[1];
    const float* W1      = (const float*)d_in[2];
    const float* b1      = (const float*)d_in[3];
    const float* W2      = (const float*)d_in[4];
    const float* b2      = (const float*)d_in[5];
    const float* gamma   = (const float*)d_in[6];
    const float* beta    = (const float*)d_in[7];
    const float* alpha   = (const float*)d_in[8];
    float* out = (float*)d_out;

    float* pz;
    uint16_t *pxh, *pxl, *pzh, *phh, *ptf, *pw1h, *pw2h;
    cudaGetSymbolAddress((void**)&pz,   g_z);
    cudaGetSymbolAddress((void**)&pxh,  g_xh);
    cudaGetSymbolAddress((void**)&pxl,  g_xl);
    cudaGetSymbolAddress((void**)&pzh,  g_zh);
    cudaGetSymbolAddress((void**)&phh,  g_hh);
    cudaGetSymbolAddress((void**)&ptf,  g_tf);
    cudaGetSymbolAddress((void**)&pw1h, g_w1h);
    cudaGetSymbolAddress((void**)&pw2h, g_w2h);

    cudaFuncSetAttribute((const void*)gemm_big<0, 2>, cudaFuncAttributeMaxDynamicSharedMemorySize, 3 * 32768);
    cudaFuncSetAttribute((const void*)gemm_big<1, 1>, cudaFuncAttributeMaxDynamicSharedMemorySize, 3 * 24576);
    cudaFuncSetAttribute((const void*)gemm_big<2, 1>, cudaFuncAttributeMaxDynamicSharedMemorySize, 3 * 24576);

    // prepasses (3 launches)
    convert_split_f16_kernel<<<(M_TOK * DIM) / 1024, 256>>>(x, pxh, pxl);
    transpose_f16_kernel<<<dim3(DIM / 32, DIM / 32), dim3(32, 8)>>>(theta_Q, ptf, DIM, DIM);
    transpose_bf_dual_kernel<<<dim3((DIM / 32) * (HID / 32), 1, 2), dim3(32, 8)>>>(
        W1, pw1h, DIM, HID, W2, pw2h, HID, DIM);

    // z = x @ theta  (fp16 2-term; write z fp32 + bf16(z))
    gemm_big<0, 2><<<dim3(DIM / 256, M_TOK / 128), 256, 3 * 32768>>>(
        pxh, pxl, ptf, nullptr, pz, pzh, DIM, DIM);
    // h = gelu(z @ W1 + b1)  (bf16 1-term; write bf16)
    gemm_big<1, 1><<<dim3(HID / 256, M_TOK / 128), 256, 3 * 24576>>>(
        pzh, nullptr, pw1h, b1, nullptr, phh, DIM, HID);
    // y = h @ W2 + b2  (bf16 1-term) -> d_out fp32
    gemm_big<2, 1><<<dim3(DIM / 256, M_TOK / 128), 256, 3 * 24576>>>(
        phh, nullptr, pw2h, b2, out, nullptr, HID, DIM);

    // out = z + tanh(alpha) * LN(y)
    ln_residual_kernel<<<M_TOK, 256>>>(pz, gamma, beta, alpha, out);
}

// round 16
// speedup vs baseline: 1.1820x; 1.1820x over previous
#include <cuda_runtime.h>
#include <cuda_bf16.h>
#include <cuda_fp16.h>
#include <math.h>
#include <stdint.h>

// Dims fixed by dataset: B=2,V=8,T=512,D=1024,H=4096 -> M=8192 rows.
#define M_TOK 8192
#define DIM   1024
#define HID   4096

// ---------------- scratch (device globals) --------------------------------------
__device__ float    g_z [(size_t)M_TOK * DIM];   // z fp32 (for residual)
__device__ uint16_t g_xh[(size_t)M_TOK * DIM];   // fp16 hi of x
__device__ uint16_t g_xl[(size_t)M_TOK * DIM];   // fp16 lo of x
__device__ uint16_t g_zh[(size_t)M_TOK * DIM];   // bf16(z) for GEMM1
__device__ uint16_t g_hh[(size_t)M_TOK * HID];   // bf16(h) for GEMM2
__device__ uint16_t g_tf [(size_t)DIM * DIM];    // fp16(theta^T) [N=D,K=D]
__device__ uint16_t g_w1h[(size_t)HID * DIM];    // bf16(W1^T) [H,D]
__device__ uint16_t g_w2h[(size_t)DIM * HID];    // bf16(W2^T) [D,H]

// ---------------- helpers -------------------------------------------------------
__device__ __forceinline__ uint32_t smem_u32(const void* p) {
    uint32_t a;
    asm("{ .reg .u64 t; cvta.to.shared.u64 t, %1; cvt.u32.u64 %0, t; }" : "=r"(a) : "l"(p));
    return a;
}

__device__ __forceinline__ float gelu_exact(float v) {
    return 0.5f * v * (1.0f + erff(v * 0.70710678118654752f));
}

__device__ __forceinline__ uint16_t to_bf(float v) {
    __nv_bfloat16 b = __float2bfloat16_rn(v);
    return *reinterpret_cast<uint16_t*>(&b);
}

__device__ __forceinline__ uint16_t to_h16(float v) {
    __half h = __float2half_rn(v);
    return *reinterpret_cast<uint16_t*>(&h);
}

__device__ __forceinline__ void split_h16(float v, uint16_t& h, uint16_t& l) {
    __half hh = __float2half_rn(v);
    float fh = __half2float(hh);
    __half hl = __float2half_rn(v - fh);
    h = *reinterpret_cast<uint16_t*>(&hh);
    l = *reinterpret_cast<uint16_t*>(&hl);
}

__device__ __forceinline__ void ldsm4(uint32_t (&r)[4], uint32_t addr) {
    asm volatile("ldmatrix.sync.aligned.m8n8.x4.shared.b16 {%0,%1,%2,%3}, [%4];"
        : "=r"(r[0]), "=r"(r[1]), "=r"(r[2]), "=r"(r[3]) : "r"(addr));
}

__device__ __forceinline__ void mma_bf16(float (&c)[4], const uint32_t (&a)[4],
                                         uint32_t b0, uint32_t b1) {
    asm volatile(
        "mma.sync.aligned.m16n8k16.row.col.f32.bf16.bf16.f32 "
        "{%0,%1,%2,%3}, {%4,%5,%6,%7}, {%8,%9}, {%0,%1,%2,%3};"
        : "+f"(c[0]), "+f"(c[1]), "+f"(c[2]), "+f"(c[3])
        : "r"(a[0]), "r"(a[1]), "r"(a[2]), "r"(a[3]), "r"(b0), "r"(b1));
}

__device__ __forceinline__ void mma_f16(float (&c)[4], const uint32_t (&a)[4],
                                        uint32_t b0, uint32_t b1) {
    asm volatile(
        "mma.sync.aligned.m16n8k16.row.col.f32.f16.f16.f32 "
        "{%0,%1,%2,%3}, {%4,%5,%6,%7}, {%8,%9}, {%0,%1,%2,%3};"
        : "+f"(c[0]), "+f"(c[1]), "+f"(c[2]), "+f"(c[3])
        : "r"(a[0]), "r"(a[1]), "r"(a[2]), "r"(a[3]), "r"(b0), "r"(b1));
}

#define CP16(dst, src) \
    asm volatile("cp.async.cg.shared.global [%0], [%1], 16;" :: "r"(dst), "l"(src))
#define CP_COMMIT() asm volatile("cp.async.commit_group;")
#define CP_WAIT2()  asm volatile("cp.async.wait_group 2;")

// ---------------- pre-pass kernels (3 launches) ---------------------------------
__global__ __launch_bounds__(256) void convert_split_f16_kernel(
    const float* __restrict__ in, uint16_t* __restrict__ hi, uint16_t* __restrict__ lo)
{
    size_t i = ((size_t)blockIdx.x * 256 + threadIdx.x) * 4;
    float4 v = *reinterpret_cast<const float4*>(in + i);
    ushort4 h, l;
    split_h16(v.x, h.x, l.x);
    split_h16(v.y, h.y, l.y);
    split_h16(v.z, h.z, l.z);
    split_h16(v.w, h.w, l.w);
    *reinterpret_cast<ushort4*>(hi + i) = h;
    *reinterpret_cast<ushort4*>(lo + i) = l;
}

__global__ __launch_bounds__(256) void transpose_f16_kernel(
    const float* __restrict__ W, uint16_t* __restrict__ oh, int K, int N)
{
    __shared__ float tile[32][33];
    const int tx = threadIdx.x, ty = threadIdx.y;
    const int n0 = blockIdx.x * 32, k0 = blockIdx.y * 32;
#pragma unroll
    for (int i = 0; i < 4; i++)
        tile[ty + i * 8][tx] = W[(size_t)(k0 + ty + i * 8) * N + (n0 + tx)];
    __syncthreads();
#pragma unroll
    for (int i = 0; i < 4; i++) {
        float v = tile[tx][ty + i * 8];
        oh[(size_t)(n0 + ty + i * 8) * K + (k0 + tx)] = to_h16(v);
    }
}

__global__ __launch_bounds__(256) void transpose_bf_dual_kernel(
    const float* __restrict__ W1, uint16_t* __restrict__ o1, int K1, int N1,
    const float* __restrict__ W2, uint16_t* __restrict__ o2, int K2, int N2)
{
    const float* W = (blockIdx.z == 0) ? W1 : W2;
    uint16_t*   o  = (blockIdx.z == 0) ? o1 : o2;
    const int K    = (blockIdx.z == 0) ? K1 : K2;
    const int N    = (blockIdx.z == 0) ? N1 : N2;
    const int nx = N / 32;
    const int b  = blockIdx.x;
    const int bxx = b % nx, byy = b / nx;

    __shared__ float tile[32][33];
    const int tx = threadIdx.x, ty = threadIdx.y;
    const int n0 = bxx * 32, k0 = byy * 32;
#pragma unroll
    for (int i = 0; i < 4; i++)
        tile[ty + i * 8][tx] = W[(size_t)(k0 + ty + i * 8) * N + (n0 + tx)];
    __syncthreads();
#pragma unroll
    for (int i = 0; i < 4; i++) {
        float v = tile[tx][ty + i * 8];
        o[(size_t)(n0 + ty + i * 8) * K + (k0 + tx)] = to_bf(v);
    }
}

// ---------------- GEMM0: z = x @ theta^T (fp16 2-term, big tile) ----------------
// A [M,K] fp16 hi/lo, B [N,K] fp16. CTA 128m x 256n, BK=32, 8 warps (64x64 warp).
// Stage 32KB: Ahi[0,8K) Alo[8K,16K) B[16K,32K). Rows 64B, chunk c at c^((r>>1)&3).
// B fragment loaded ONCE per g and reused for hi and lo mma.
__global__ __launch_bounds__(256, 1) void gemm_z(
    const uint16_t* __restrict__ Ah, const uint16_t* __restrict__ Al,
    const uint16_t* __restrict__ B,
    float* __restrict__ outF, uint16_t* __restrict__ outH,
    int K, int N)
{
    constexpr uint32_t STG = 32768u;
    extern __shared__ __align__(1024) char smem[];
    const uint32_t sb = smem_u32(smem);
    const int tid = threadIdx.x;
    const int wid = tid >> 5, lane = tid & 31;
    const int bx = blockIdx.x, by = blockIdx.y;
    const int NKC = K >> 5;

    const uint16_t* A0h = Ah + (size_t)(by * 128) * K;
    const uint16_t* A0l = Al + (size_t)(by * 128) * K;
    const uint16_t* B0  = B + (size_t)(bx * 256) * K;

    const int srow0 = tid >> 2, sc = tid & 3;          // srow0: 0..63
    auto swz = [&](int r) -> uint32_t {
        return (uint32_t)(r * 64 + ((sc ^ ((r >> 1) & 3)) << 4));
    };

    auto issue = [&](int s) {
        if (s < NKC) {
            const int kof = s * 32 + sc * 8;
            const uint32_t base = sb + (uint32_t)(s % 3) * STG;
            const size_t oa0 = (size_t)srow0 * K + kof;
            const size_t oa1 = (size_t)(srow0 + 64) * K + kof;
            CP16(base + swz(srow0),      A0h + oa0);
            CP16(base + swz(srow0 + 64), A0h + oa1);
            CP16(base + 8192 + swz(srow0),      A0l + oa0);
            CP16(base + 8192 + swz(srow0 + 64), A0l + oa1);
            CP16(base + 16384 + swz(srow0),       B0 + oa0);
            CP16(base + 16384 + swz(srow0 + 64),  B0 + oa1);
            CP16(base + 16384 + swz(srow0 + 128), B0 + (size_t)(srow0 + 128) * K + kof);
            CP16(base + 16384 + swz(srow0 + 192), B0 + (size_t)(srow0 + 192) * K + kof);
        }
        CP_COMMIT();
    };

    issue(0);
    issue(1);
    issue(2);

    const int wm = wid >> 2;          // 0..1 -> m offset wm*64
    const int wn = wid & 3;           // 0..3 -> n offset wn*64
    const int a_r = (lane & 7) + ((lane >> 3) & 1) * 8;
    const int a_c = lane >> 4;
    const int b_r = (lane & 7) + ((lane >> 4) << 3);
    const int b_c = (lane >> 3) & 1;

    float c[4][8][4];
#pragma unroll
    for (int mf = 0; mf < 4; mf++)
#pragma unroll
        for (int nf = 0; nf < 8; nf++)
#pragma unroll
            for (int j = 0; j < 4; j++) c[mf][nf][j] = 0.0f;

    for (int kc = 0; kc < NKC; kc++) {
        CP_WAIT2();
        __syncthreads();
        const uint32_t buf = sb + (uint32_t)(kc % 3) * STG;
#pragma unroll
        for (int ks = 0; ks < 2; ks++) {
            uint32_t ah[4][4], al[4][4];
#pragma unroll
            for (int mf = 0; mf < 4; mf++) {
                const int r = wm * 64 + mf * 16 + a_r;
                const uint32_t ad = buf + (uint32_t)(r * 64 +
                                   (((2 * ks + a_c) ^ ((r >> 1) & 3)) << 4));
                ldsm4(ah[mf], ad);
                ldsm4(al[mf], ad + 8192);
            }
#pragma unroll
            for (int g = 0; g < 4; g++) {
                const int r = wn * 64 + g * 16 + b_r;
                const uint32_t bd = buf + 16384 + (uint32_t)(r * 64 +
                                   (((2 * ks + b_c) ^ ((r >> 1) & 3)) << 4));
                uint32_t b[4];
                ldsm4(b, bd);
#pragma unroll
                for (int mf = 0; mf < 4; mf++) {
                    mma_f16(c[mf][2 * g + 0], ah[mf], b[0], b[1]);
                    mma_f16(c[mf][2 * g + 1], ah[mf], b[2], b[3]);
                }
#pragma unroll
                for (int mf = 0; mf < 4; mf++) {
                    mma_f16(c[mf][2 * g + 0], al[mf], b[0], b[1]);
                    mma_f16(c[mf][2 * g + 1], al[mf], b[2], b[3]);
                }
            }
        }
        __syncthreads();
        issue(kc + 3);
    }

    const int r0 = by * 128 + wm * 64 + (lane >> 2);
    const int c0 = bx * 256 + wn * 64 + (lane & 3) * 2;
#pragma unroll
    for (int mf = 0; mf < 4; mf++) {
#pragma unroll
        for (int nf = 0; nf < 8; nf++) {
            const int col = c0 + nf * 8;
#pragma unroll
            for (int half = 0; half < 2; half++) {
                const int row = r0 + mf * 16 + half * 8;
                const float v0 = c[mf][nf][2 * half + 0];
                const float v1 = c[mf][nf][2 * half + 1];
                const size_t o = (size_t)row * N + col;
                *reinterpret_cast<float2*>(outF + o) = make_float2(v0, v1);
                *reinterpret_cast<uint32_t*>(outH + o) =
                    (uint32_t)to_bf(v0) | ((uint32_t)to_bf(v1) << 16);
            }
        }
    }
}

// ---------------- GEMM1/2: bf16 1-term, 128x128, 2 CTAs/SM, BK=64 ---------------
// Stage 32KB: A[0,16K) B[16K,32K). Rows 128B (64 bf16), chunk c (0..7) at c^(r&7).
// OP 1: +bias, exact GELU, write bf16   (h)
// OP 2: +bias, write fp32               (y -> d_out)
template <int OP>
__global__ __launch_bounds__(256, 2) void gemm_bf(
    const uint16_t* __restrict__ A, const uint16_t* __restrict__ B,
    const float* __restrict__ bias,
    float* __restrict__ outF, uint16_t* __restrict__ outH,
    int K, int N)
{
    constexpr uint32_t STG = 32768u;
    extern __shared__ __align__(1024) char smem[];
    const uint32_t sb = smem_u32(smem);
    const int tid = threadIdx.x;
    const int wid = tid >> 5, lane = tid & 31;
    const int bx = blockIdx.x, by = blockIdx.y;
    const int NKC = K >> 6;

    const uint16_t* A0 = A + (size_t)(by * 128) * K;
    const uint16_t* B0 = B + (size_t)(bx * 128) * K;

    const int srow = tid >> 3, sc8 = tid & 7;          // srow: 0..31, sc8: 0..7
    auto swz = [&](int r) -> uint32_t {
        return (uint32_t)(r * 128 + ((sc8 ^ (r & 7)) << 4));
    };

    auto issue = [&](int s) {
        if (s < NKC) {
            const int kof = s * 64 + sc8 * 8;
            const uint32_t base = sb + (uint32_t)(s % 3) * STG;
#pragma unroll
            for (int p = 0; p < 4; p++) {
                const int r = srow + p * 32;
                const size_t o = (size_t)r * K + kof;
                CP16(base + swz(r),         A0 + o);
                CP16(base + 16384 + swz(r), B0 + o);
            }
        }
        CP_COMMIT();
    };

    issue(0);
    issue(1);
    issue(2);

    const int wm = wid >> 1;          // 0..3 -> m offset wm*32
    const int wn = wid & 1;           // 0..1 -> n offset wn*64
    const int a_r = (lane & 7) + ((lane >> 3) & 1) * 8;
    const int a_c = lane >> 4;
    const int b_r = (lane & 7) + ((lane >> 4) << 3);
    const int b_c = (lane >> 3) & 1;

    float c[2][8][4];
#pragma unroll
    for (int mf = 0; mf < 2; mf++)
#pragma unroll
        for (int nf = 0; nf < 8; nf++)
#pragma unroll
            for (int j = 0; j < 4; j++) c[mf][nf][j] = 0.0f;

    for (int kc = 0; kc < NKC; kc++) {
        CP_WAIT2();
        __syncthreads();
        const uint32_t buf = sb + (uint32_t)(kc % 3) * STG;
#pragma unroll
        for (int ks = 0; ks < 4; ks++) {
            uint32_t af[2][4];
#pragma unroll
            for (int mf = 0; mf < 2; mf++) {
                const int r = wm * 32 + mf * 16 + a_r;
                const uint32_t ad = buf + (uint32_t)(r * 128 +
                                   (((2 * ks + a_c) ^ (r & 7)) << 4));
                ldsm4(af[mf], ad);
            }
#pragma unroll
            for (int g = 0; g < 4; g++) {
                const int r = wn * 64 + g * 16 + b_r;
                const uint32_t bd = buf + 16384 + (uint32_t)(r * 128 +
                                   (((2 * ks + b_c) ^ (r & 7)) << 4));
                uint32_t b[4];
                ldsm4(b, bd);
#pragma unroll
                for (int mf = 0; mf < 2; mf++) {
                    mma_bf16(c[mf][2 * g + 0], af[mf], b[0], b[1]);
                    mma_bf16(c[mf][2 * g + 1], af[mf], b[2], b[3]);
                }
            }
        }
        __syncthreads();
        issue(kc + 3);
    }

    const int r0 = by * 128 + wm * 32 + (lane >> 2);
    const int c0 = bx * 128 + wn * 64 + (lane & 3) * 2;
#pragma unroll
    for (int mf = 0; mf < 2; mf++) {
#pragma unroll
        for (int nf = 0; nf < 8; nf++) {
            const int col = c0 + nf * 8;
            const float bv0 = bias[col];
            const float bv1 = bias[col + 1];
#pragma unroll
            for (int half = 0; half < 2; half++) {
                const int row = r0 + mf * 16 + half * 8;
                float v0 = c[mf][nf][2 * half + 0] + bv0;
                float v1 = c[mf][nf][2 * half + 1] + bv1;
                const size_t o = (size_t)row * N + col;
                if (OP == 1) {
                    v0 = gelu_exact(v0);
                    v1 = gelu_exact(v1);
                    *reinterpret_cast<uint32_t*>(outH + o) =
                        (uint32_t)to_bf(v0) | ((uint32_t)to_bf(v1) << 16);
                } else {
                    *reinterpret_cast<float2*>(outF + o) = make_float2(v0, v1);
                }
            }
        }
    }
}

// ---------------- LayerNorm + residual -----------------------------------------
__global__ __launch_bounds__(256) void ln_residual_kernel(
    const float* __restrict__ Z,
    const float* __restrict__ gamma, const float* __restrict__ beta,
    const float* __restrict__ alpha, float* __restrict__ out)
{
    const int row = blockIdx.x;
    const int tid = threadIdx.x;
    float4* orow = reinterpret_cast<float4*>(out + (size_t)row * DIM);
    const float4* zrow = reinterpret_cast<const float4*>(Z + (size_t)row * DIM);

    float4 v = orow[tid];

    __shared__ float red1[8];
    __shared__ float red2[8];

    float s = v.x + v.y + v.z + v.w;
#pragma unroll
    for (int o = 16; o > 0; o >>= 1) s += __shfl_xor_sync(0xffffffffu, s, o);
    if ((tid & 31) == 0) red1[tid >> 5] = s;
    __syncthreads();
    float tot = 0.0f;
#pragma unroll
    for (int i = 0; i < 8; i++) tot += red1[i];
    const float mu = tot * (1.0f / (float)DIM);

    const float dx = v.x - mu, dy = v.y - mu, dz = v.z - mu, dw = v.w - mu;
    float ss = dx * dx + dy * dy + dz * dz + dw * dw;
#pragma unroll
    for (int o = 16; o > 0; o >>= 1) ss += __shfl_xor_sync(0xffffffffu, ss, o);
    if ((tid & 31) == 0) red2[tid >> 5] = ss;
    __syncthreads();
    float tot2 = 0.0f;
#pragma unroll
    for (int i = 0; i < 8; i++) tot2 += red2[i];
    const float rstd = rsqrtf(tot2 * (1.0f / (float)DIM) + 1e-5f);

    const float4 g  = reinterpret_cast<const float4*>(gamma)[tid];
    const float4 b  = reinterpret_cast<const float4*>(beta)[tid];
    const float4 al = reinterpret_cast<const float4*>(alpha)[tid];
    const float4 z4 = zrow[tid];

    float4 o4;
    o4.x = z4.x + tanhf(al.x) * (dx * rstd * g.x + b.x);
    o4.y = z4.y + tanhf(al.y) * (dy * rstd * g.y + b.y);
    o4.z = z4.z + tanhf(al.z) * (dz * rstd * g.z + b.z);
    o4.w = z4.w + tanhf(al.w) * (dw * rstd * g.w + b.w);
    orow[tid] = o4;
}

// ---------------- launch --------------------------------------------------------
extern "C" void kernel_launch(void* const* d_in, const int* in_sizes, int n_in,
                              void* d_out, int out_size)
{
    const float* x       = (const float*)d_in[0];
    const float* theta_Q = (const float*)d_in[1];
    const float* W1      = (const float*)d_in[2];
    const float* b1      = (const float*)d_in[3];
    const float* W2      = (const float*)d_in[4];
    const float* b2      = (const float*)d_in[5];
    const float* gamma   = (const float*)d_in[6];
    const float* beta    = (const float*)d_in[7];
    const float* alpha   = (const float*)d_in[8];
    float* out = (float*)d_out;

    float* pz;
    uint16_t *pxh, *pxl, *pzh, *phh, *ptf, *pw1h, *pw2h;
    cudaGetSymbolAddress((void**)&pz,   g_z);
    cudaGetSymbolAddress((void**)&pxh,  g_xh);
    cudaGetSymbolAddress((void**)&pxl,  g_xl);
    cudaGetSymbolAddress((void**)&pzh,  g_zh);
    cudaGetSymbolAddress((void**)&phh,  g_hh);
    cudaGetSymbolAddress((void**)&ptf,  g_tf);
    cudaGetSymbolAddress((void**)&pw1h, g_w1h);
    cudaGetSymbolAddress((void**)&pw2h, g_w2h);

    cudaFuncSetAttribute((const void*)gemm_z,     cudaFuncAttributeMaxDynamicSharedMemorySize, 3 * 32768);
    cudaFuncSetAttribute((const void*)gemm_bf<1>, cudaFuncAttributeMaxDynamicSharedMemorySize, 3 * 32768);
    cudaFuncSetAttribute((const void*)gemm_bf<2>, cudaFuncAttributeMaxDynamicSharedMemorySize, 3 * 32768);

    // prepasses (3 launches)
    convert_split_f16_kernel<<<(M_TOK * DIM) / 1024, 256>>>(x, pxh, pxl);
    transpose_f16_kernel<<<dim3(DIM / 32, DIM / 32), dim3(32, 8)>>>(theta_Q, ptf, DIM, DIM);
    transpose_bf_dual_kernel<<<dim3((DIM / 32) * (HID / 32), 1, 2), dim3(32, 8)>>>(
        W1, pw1h, DIM, HID, W2, pw2h, HID, DIM);

    // z = x @ theta  (fp16 2-term big tile; write z fp32 + bf16(z))
    gemm_z<<<dim3(DIM / 256, M_TOK / 128), 256, 3 * 32768>>>(
        pxh, pxl, ptf, pz, pzh, DIM, DIM);
    // h = gelu(z @ W1 + b1)  (bf16; write bf16)
    gemm_bf<1><<<dim3(HID / 128, M_TOK / 128), 256, 3 * 32768>>>(
        pzh, pw1h, b1, nullptr, phh, DIM, HID);
    // y = h @ W2 + b2  (bf16) -> d_out fp32
    gemm_bf<2><<<dim3(DIM / 128, M_TOK / 128), 256, 3 * 32768>>>(
        phh, pw2h, b2, out, nullptr, HID, DIM);

    // out = z + tanh(alpha) * LN(y)
    ln_residual_kernel<<<M_TOK, 256>>>(pz, gamma, beta, alpha, out);
}

// round 17
// speedup vs baseline: 1.1960x; 1.0118x over previous
#include <cuda_runtime.h>
#include <cuda_bf16.h>
#include <cuda_fp16.h>
#include <math.h>
#include <stdint.h>

// Dims fixed by dataset: B=2,V=8,T=512,D=1024,H=4096 -> M=8192 rows.
#define M_TOK 8192
#define DIM   1024
#define HID   4096

// ---------------- scratch (device globals) --------------------------------------
__device__ float    g_z [(size_t)M_TOK * DIM];      // z fp32 (for residual)
__device__ uint16_t g_xs[(size_t)M_TOK * 2 * DIM];  // fp16 [M,2048]: hi cols 0-1023, lo 1024-2047
__device__ uint16_t g_zh[(size_t)M_TOK * DIM];      // bf16(z) for GEMM1
__device__ uint16_t g_hh[(size_t)M_TOK * HID];      // bf16(h) for GEMM2
__device__ uint16_t g_tf [(size_t)DIM * DIM];       // fp16(theta^T) [N=D,K=D]
__device__ uint16_t g_w1h[(size_t)HID * DIM];       // bf16(W1^T) [H,D]
__device__ uint16_t g_w2h[(size_t)DIM * HID];       // bf16(W2^T) [D,H]

// ---------------- helpers -------------------------------------------------------
__device__ __forceinline__ uint32_t smem_u32(const void* p) {
    uint32_t a;
    asm("{ .reg .u64 t; cvta.to.shared.u64 t, %1; cvt.u32.u64 %0, t; }" : "=r"(a) : "l"(p));
    return a;
}

__device__ __forceinline__ float gelu_exact(float v) {
    return 0.5f * v * (1.0f + erff(v * 0.70710678118654752f));
}

__device__ __forceinline__ uint16_t to_bf(float v) {
    __nv_bfloat16 b = __float2bfloat16_rn(v);
    return *reinterpret_cast<uint16_t*>(&b);
}

__device__ __forceinline__ uint16_t to_h16(float v) {
    __half h = __float2half_rn(v);
    return *reinterpret_cast<uint16_t*>(&h);
}

__device__ __forceinline__ void split_h16(float v, uint16_t& h, uint16_t& l) {
    __half hh = __float2half_rn(v);
    float fh = __half2float(hh);
    __half hl = __float2half_rn(v - fh);
    h = *reinterpret_cast<uint16_t*>(&hh);
    l = *reinterpret_cast<uint16_t*>(&hl);
}

__device__ __forceinline__ void ldsm4(uint32_t (&r)[4], uint32_t addr) {
    asm volatile("ldmatrix.sync.aligned.m8n8.x4.shared.b16 {%0,%1,%2,%3}, [%4];"
        : "=r"(r[0]), "=r"(r[1]), "=r"(r[2]), "=r"(r[3]) : "r"(addr));
}

__device__ __forceinline__ void mma_bf16(float (&c)[4], const uint32_t (&a)[4],
                                         uint32_t b0, uint32_t b1) {
    asm volatile(
        "mma.sync.aligned.m16n8k16.row.col.f32.bf16.bf16.f32 "
        "{%0,%1,%2,%3}, {%4,%5,%6,%7}, {%8,%9}, {%0,%1,%2,%3};"
        : "+f"(c[0]), "+f"(c[1]), "+f"(c[2]), "+f"(c[3])
        : "r"(a[0]), "r"(a[1]), "r"(a[2]), "r"(a[3]), "r"(b0), "r"(b1));
}

__device__ __forceinline__ void mma_f16(float (&c)[4], const uint32_t (&a)[4],
                                        uint32_t b0, uint32_t b1) {
    asm volatile(
        "mma.sync.aligned.m16n8k16.row.col.f32.f16.f16.f32 "
        "{%0,%1,%2,%3}, {%4,%5,%6,%7}, {%8,%9}, {%0,%1,%2,%3};"
        : "+f"(c[0]), "+f"(c[1]), "+f"(c[2]), "+f"(c[3])
        : "r"(a[0]), "r"(a[1]), "r"(a[2]), "r"(a[3]), "r"(b0), "r"(b1));
}

#define CP16(dst, src) \
    asm volatile("cp.async.cg.shared.global [%0], [%1], 16;" :: "r"(dst), "l"(src))
#define CP_COMMIT() asm volatile("cp.async.commit_group;")
#define CP_WAIT2()  asm volatile("cp.async.wait_group 2;")

// ---------------- pre-pass kernels (3 launches) ---------------------------------
// x fp32 [M,1024] -> g_xs fp16 [M,2048] (hi | lo)
__global__ __launch_bounds__(256) void convert_split_f16_kernel(
    const float* __restrict__ in, uint16_t* __restrict__ xs)
{
    size_t i = ((size_t)blockIdx.x * 256 + threadIdx.x) * 4;
    const size_t row = i >> 10, col = i & 1023;
    float4 v = *reinterpret_cast<const float4*>(in + i);
    ushort4 h, l;
    split_h16(v.x, h.x, l.x);
    split_h16(v.y, h.y, l.y);
    split_h16(v.z, h.z, l.z);
    split_h16(v.w, h.w, l.w);
    *reinterpret_cast<ushort4*>(xs + row * 2048 + col) = h;
    *reinterpret_cast<ushort4*>(xs + row * 2048 + 1024 + col) = l;
}

__global__ __launch_bounds__(256) void transpose_f16_kernel(
    const float* __restrict__ W, uint16_t* __restrict__ oh, int K, int N)
{
    __shared__ float tile[32][33];
    const int tx = threadIdx.x, ty = threadIdx.y;
    const int n0 = blockIdx.x * 32, k0 = blockIdx.y * 32;
#pragma unroll
    for (int i = 0; i < 4; i++)
        tile[ty + i * 8][tx] = W[(size_t)(k0 + ty + i * 8) * N + (n0 + tx)];
    __syncthreads();
#pragma unroll
    for (int i = 0; i < 4; i++) {
        float v = tile[tx][ty + i * 8];
        oh[(size_t)(n0 + ty + i * 8) * K + (k0 + tx)] = to_h16(v);
    }
}

__global__ __launch_bounds__(256) void transpose_bf_dual_kernel(
    const float* __restrict__ W1, uint16_t* __restrict__ o1, int K1, int N1,
    const float* __restrict__ W2, uint16_t* __restrict__ o2, int K2, int N2)
{
    const float* W = (blockIdx.z == 0) ? W1 : W2;
    uint16_t*   o  = (blockIdx.z == 0) ? o1 : o2;
    const int K    = (blockIdx.z == 0) ? K1 : K2;
    const int N    = (blockIdx.z == 0) ? N1 : N2;
    const int nx = N / 32;
    const int b  = blockIdx.x;
    const int bxx = b % nx, byy = b / nx;

    __shared__ float tile[32][33];
    const int tx = threadIdx.x, ty = threadIdx.y;
    const int n0 = bxx * 32, k0 = byy * 32;
#pragma unroll
    for (int i = 0; i < 4; i++)
        tile[ty + i * 8][tx] = W[(size_t)(k0 + ty + i * 8) * N + (n0 + tx)];
    __syncthreads();
#pragma unroll
    for (int i = 0; i < 4; i++) {
        float v = tile[tx][ty + i * 8];
        o[(size_t)(n0 + ty + i * 8) * K + (k0 + tx)] = to_bf(v);
    }
}

// ---------------- unified GEMM: 128x128, BK=64, 8 warps, 2 CTAs/SM --------------
// C[M,N] = A @ B^T; A [M,K] K-major, B [N,KB] K-major (KB = K, or wrapped).
// Stage 32KB: A[0,16K) B[16K,32K). Rows 128B (64 elems), chunk c (0..7) at c^(r&7).
// MMT 0 = bf16, 1 = fp16.
// WRAPB: B has 1024 K-cols, read col (kof & 1023)  (concat-K trick for GEMM0).
// OP 0: write fp32 + bf16        (z)
// OP 1: +bias, exact GELU, bf16  (h)
// OP 2: +bias, fp32              (y -> d_out)
template <int OP, int MMT, int WRAPB>
__global__ __launch_bounds__(256, 2) void gemm_u(
    const uint16_t* __restrict__ A, const uint16_t* __restrict__ B,
    const float* __restrict__ bias,
    float* __restrict__ outF, uint16_t* __restrict__ outH,
    int K, int N)
{
    constexpr uint32_t STG = 32768u;
    extern __shared__ __align__(1024) char smem[];
    const uint32_t sb = smem_u32(smem);
    const int tid = threadIdx.x;
    const int wid = tid >> 5, lane = tid & 31;
    const int bx = blockIdx.x, by = blockIdx.y;
    const int NKC = K >> 6;

    const uint16_t* A0 = A + (size_t)(by * 128) * K;
    const uint16_t* B0 = B + (size_t)(bx * 128) * (WRAPB ? 1024 : K);

    const int srow = tid >> 3, sc8 = tid & 7;          // srow: 0..31, sc8: 0..7
    auto swz = [&](int r) -> uint32_t {
        return (uint32_t)(r * 128 + ((sc8 ^ (r & 7)) << 4));
    };

    auto issue = [&](int s) {
        if (s < NKC) {
            const int kof = s * 64 + sc8 * 8;
            const int kofb = WRAPB ? (kof & 1023) : kof;
            const uint32_t base = sb + (uint32_t)(s % 3) * STG;
#pragma unroll
            for (int p = 0; p < 4; p++) {
                const int r = srow + p * 32;
                CP16(base + swz(r),         A0 + (size_t)r * K + kof);
                CP16(base + 16384 + swz(r), B0 + (size_t)r * (WRAPB ? 1024 : K) + kofb);
            }
        }
        CP_COMMIT();
    };

    issue(0);
    issue(1);
    issue(2);

    const int wm = wid >> 1;          // 0..3 -> m offset wm*32
    const int wn = wid & 1;           // 0..1 -> n offset wn*64
    const int a_r = (lane & 7) + ((lane >> 3) & 1) * 8;
    const int a_c = lane >> 4;
    const int b_r = (lane & 7) + ((lane >> 4) << 3);
    const int b_c = (lane >> 3) & 1;

    float c[2][8][4];
#pragma unroll
    for (int mf = 0; mf < 2; mf++)
#pragma unroll
        for (int nf = 0; nf < 8; nf++)
#pragma unroll
            for (int j = 0; j < 4; j++) c[mf][nf][j] = 0.0f;

    for (int kc = 0; kc < NKC; kc++) {
        CP_WAIT2();
        __syncthreads();
        const uint32_t buf = sb + (uint32_t)(kc % 3) * STG;
#pragma unroll
        for (int ks = 0; ks < 4; ks++) {
            uint32_t af[2][4];
#pragma unroll
            for (int mf = 0; mf < 2; mf++) {
                const int r = wm * 32 + mf * 16 + a_r;
                const uint32_t ad = buf + (uint32_t)(r * 128 +
                                   (((2 * ks + a_c) ^ (r & 7)) << 4));
                ldsm4(af[mf], ad);
            }
#pragma unroll
            for (int g = 0; g < 4; g++) {
                const int r = wn * 64 + g * 16 + b_r;
                const uint32_t bd = buf + 16384 + (uint32_t)(r * 128 +
                                   (((2 * ks + b_c) ^ (r & 7)) << 4));
                uint32_t b[4];
                ldsm4(b, bd);
#pragma unroll
                for (int mf = 0; mf < 2; mf++) {
                    if (MMT == 1) {
                        mma_f16(c[mf][2 * g + 0], af[mf], b[0], b[1]);
                        mma_f16(c[mf][2 * g + 1], af[mf], b[2], b[3]);
                    } else {
                        mma_bf16(c[mf][2 * g + 0], af[mf], b[0], b[1]);
                        mma_bf16(c[mf][2 * g + 1], af[mf], b[2], b[3]);
                    }
                }
            }
        }
        __syncthreads();
        issue(kc + 3);
    }

    const int r0 = by * 128 + wm * 32 + (lane >> 2);
    const int c0 = bx * 128 + wn * 64 + (lane & 3) * 2;
#pragma unroll
    for (int mf = 0; mf < 2; mf++) {
#pragma unroll
        for (int nf = 0; nf < 8; nf++) {
            const int col = c0 + nf * 8;
            float bv0 = 0.0f, bv1 = 0.0f;
            if (OP >= 1) { bv0 = bias[col]; bv1 = bias[col + 1]; }
#pragma unroll
            for (int half = 0; half < 2; half++) {
                const int row = r0 + mf * 16 + half * 8;
                float v0 = c[mf][nf][2 * half + 0];
                float v1 = c[mf][nf][2 * half + 1];
                const size_t o = (size_t)row * N + col;
                if (OP == 0) {
                    *reinterpret_cast<float2*>(outF + o) = make_float2(v0, v1);
                    *reinterpret_cast<uint32_t*>(outH + o) =
                        (uint32_t)to_bf(v0) | ((uint32_t)to_bf(v1) << 16);
                } else if (OP == 1) {
                    v0 = gelu_exact(v0 + bv0);
                    v1 = gelu_exact(v1 + bv1);
                    *reinterpret_cast<uint32_t*>(outH + o) =
                        (uint32_t)to_bf(v0) | ((uint32_t)to_bf(v1) << 16);
                } else {
                    *reinterpret_cast<float2*>(outF + o) = make_float2(v0 + bv0, v1 + bv1);
                }
            }
        }
    }
}

// ---------------- LayerNorm + residual -----------------------------------------
__global__ __launch_bounds__(256) void ln_residual_kernel(
    const float* __restrict__ Z,
    const float* __restrict__ gamma, const float* __restrict__ beta,
    const float* __restrict__ alpha, float* __restrict__ out)
{
    const int row = blockIdx.x;
    const int tid = threadIdx.x;
    float4* orow = reinterpret_cast<float4*>(out + (size_t)row * DIM);
    const float4* zrow = reinterpret_cast<const float4*>(Z + (size_t)row * DIM);

    float4 v = orow[tid];

    __shared__ float red1[8];
    __shared__ float red2[8];

    float s = v.x + v.y + v.z + v.w;
#pragma unroll
    for (int o = 16; o > 0; o >>= 1) s += __shfl_xor_sync(0xffffffffu, s, o);
    if ((tid & 31) == 0) red1[tid >> 5] = s;
    __syncthreads();
    float tot = 0.0f;
#pragma unroll
    for (int i = 0; i < 8; i++) tot += red1[i];
    const float mu = tot * (1.0f / (float)DIM);

    const float dx = v.x - mu, dy = v.y - mu, dz = v.z - mu, dw = v.w - mu;
    float ss = dx * dx + dy * dy + dz * dz + dw * dw;
#pragma unroll
    for (int o = 16; o > 0; o >>= 1) ss += __shfl_xor_sync(0xffffffffu, ss, o);
    if ((tid & 31) == 0) red2[tid >> 5] = ss;
    __syncthreads();
    float tot2 = 0.0f;
#pragma unroll
    for (int i = 0; i < 8; i++) tot2 += red2[i];
    const float rstd = rsqrtf(tot2 * (1.0f / (float)DIM) + 1e-5f);

    const float4 g  = reinterpret_cast<const float4*>(gamma)[tid];
    const float4 b  = reinterpret_cast<const float4*>(beta)[tid];
    const float4 al = reinterpret_cast<const float4*>(alpha)[tid];
    const float4 z4 = zrow[tid];

    float4 o4;
    o4.x = z4.x + tanhf(al.x) * (dx * rstd * g.x + b.x);
    o4.y = z4.y + tanhf(al.y) * (dy * rstd * g.y + b.y);
    o4.z = z4.z + tanhf(al.z) * (dz * rstd * g.z + b.z);
    o4.w = z4.w + tanhf(al.w) * (dw * rstd * g.w + b.w);
    orow[tid] = o4;
}

// ---------------- launch --------------------------------------------------------
extern "C" void kernel_launch(void* const* d_in, const int* in_sizes, int n_in,
                              void* d_out, int out_size)
{
    const float* x       = (const float*)d_in[0];
    const float* theta_Q = (const float*)d_in[1];
    const float* W1      = (const float*)d_in[2];
    const float* b1      = (const float*)d_in[3];
    const float* W2      = (const float*)d_in[4];
    const float* b2      = (const float*)d_in[5];
    const float* gamma   = (const float*)d_in[6];
    const float* beta    = (const float*)d_in[7];
    const float* alpha   = (const float*)d_in[8];
    float* out = (float*)d_out;

    float* pz;
    uint16_t *pxs, *pzh, *phh, *ptf, *pw1h, *pw2h;
    cudaGetSymbolAddress((void**)&pz,   g_z);
    cudaGetSymbolAddress((void**)&pxs,  g_xs);
    cudaGetSymbolAddress((void**)&pzh,  g_zh);
    cudaGetSymbolAddress((void**)&phh,  g_hh);
    cudaGetSymbolAddress((void**)&ptf,  g_tf);
    cudaGetSymbolAddress((void**)&pw1h, g_w1h);
    cudaGetSymbolAddress((void**)&pw2h, g_w2h);

    cudaFuncSetAttribute((const void*)gemm_u<0, 1, 1>, cudaFuncAttributeMaxDynamicSharedMemorySize, 3 * 32768);
    cudaFuncSetAttribute((const void*)gemm_u<1, 0, 0>, cudaFuncAttributeMaxDynamicSharedMemorySize, 3 * 32768);
    cudaFuncSetAttribute((const void*)gemm_u<2, 0, 0>, cudaFuncAttributeMaxDynamicSharedMemorySize, 3 * 32768);

    // prepasses (3 launches)
    convert_split_f16_kernel<<<(M_TOK * DIM) / 1024, 256>>>(x, pxs);
    transpose_f16_kernel<<<dim3(DIM / 32, DIM / 32), dim3(32, 8)>>>(theta_Q, ptf, DIM, DIM);
    transpose_bf_dual_kernel<<<dim3((DIM / 32) * (HID / 32), 1, 2), dim3(32, 8)>>>(
        W1, pw1h, DIM, HID, W2, pw2h, HID, DIM);

    // z = [x_hi|x_lo] @ [theta|theta]^T   (fp16 concat-K, K=2048; write z fp32 + bf16)
    gemm_u<0, 1, 1><<<dim3(DIM / 128, M_TOK / 128), 256, 3 * 32768>>>(
        pxs, ptf, nullptr, pz, pzh, 2 * DIM, DIM);
    // h = gelu(z @ W1 + b1)  (bf16; write bf16)
    gemm_u<1, 0, 0><<<dim3(HID / 128, M_TOK / 128), 256, 3 * 32768>>>(
        pzh, pw1h, b1, nullptr, phh, DIM, HID);
    // y = h @ W2 + b2  (bf16) -> d_out fp32
    gemm_u<2, 0, 0><<<dim3(DIM / 128, M_TOK / 128), 256, 3 * 32768>>>(
        phh, pw2h, b2, out, nullptr, HID, DIM);

    // out = z + tanh(alpha) * LN(y)
    ln_residual_kernel<<<M_TOK, 256>>>(pz, gamma, beta, alpha, out);
}